// round 7
// baseline (speedup 1.0000x reference)
#include <cuda_runtime.h>
#include <math.h>

#define D 512
#define ROWS_PER_BLOCK 8
#define THREADS 256            // 8 warps, 1 row per warp, 16 elems/lane
#define RATE 0.1f
#define CLIP_MAG 8.0f
#define EPS 1e-4f
#define ACOSH_MIN 1.0001f

struct F8 { float f[8]; };

// 256-bit read-only load with L2 evict-last priority (sm_103a requires the
// .v4.b64 shape for evict_last). Keeps inputs L2-resident across graph
// replays while the evict-first output stream passes through.
__device__ __forceinline__ F8 ldg256_el(const float* p) {
    unsigned long long a, b, c, d;
    asm volatile("ld.global.nc.L2::evict_last.v4.b64 {%0,%1,%2,%3}, [%4];"
                 : "=l"(a), "=l"(b), "=l"(c), "=l"(d)
                 : "l"(p));
    F8 r;
    r.f[0] = __uint_as_float((unsigned)(a));
    r.f[1] = __uint_as_float((unsigned)(a >> 32));
    r.f[2] = __uint_as_float((unsigned)(b));
    r.f[3] = __uint_as_float((unsigned)(b >> 32));
    r.f[4] = __uint_as_float((unsigned)(c));
    r.f[5] = __uint_as_float((unsigned)(c >> 32));
    r.f[6] = __uint_as_float((unsigned)(d));
    r.f[7] = __uint_as_float((unsigned)(d >> 32));
    return r;
}

__global__ __launch_bounds__(THREADS, 8)
void dropout_hyperbolic_kernel(const float* __restrict__ vecs,
                               const float* __restrict__ curvature,
                               const float* __restrict__ mask_u,
                               float* __restrict__ out)
{
    const int warp = threadIdx.x >> 5;
    const int lane = threadIdx.x & 31;
    const int row  = blockIdx.x * ROWS_PER_BLOCK + warp;

    const float* vp = vecs   + row * D;
    const float* mp = mask_u + row * D;
    float*       op = out    + row * D;

    // Chunk i (i=0,1) covers floats [i*256 + lane*8, +8): each LDG.256 is a
    // fully coalesced 1024B warp transaction. 4 loads front-batched.
    F8 v[2], m[2];
    #pragma unroll
    for (int i = 0; i < 2; i++) v[i] = ldg256_el(vp + i * 256 + lane * 8);
    #pragma unroll
    for (int i = 0; i < 2; i++) m[i] = ldg256_el(mp + i * 256 + lane * 8);

    // Row element 0 (lane 0, chunk 0, f[0]) is the hyperboloid coordinate:
    // excluded from both sums; its output is overwritten below anyway.
    if (lane == 0) v[0].f[0] = 0.0f;

    // Pack keep decisions into a 16-bit mask (bit 8*i+j) and accumulate
    // s = sum v^2, sk = sum v^2*keep in the same pass.
    unsigned bits = 0u;
    float s_loc = 0.0f, sk_loc = 0.0f;
    #pragma unroll
    for (int i = 0; i < 2; i++) {
        #pragma unroll
        for (int j = 0; j < 8; j++) {
            bool b = (m[i].f[j] >= RATE);
            bits |= (unsigned(b) << (8*i + j));
            float x = v[i].f[j] * v[i].f[j];
            s_loc += x;
            sk_loc += b ? x : 0.0f;
        }
    }

    // Butterfly reduce — all lanes end with the row totals. No barriers.
    #pragma unroll
    for (int off = 16; off > 0; off >>= 1) {
        s_loc  += __shfl_xor_sync(0xFFFFFFFFu, s_loc,  off);
        sk_loc += __shfl_xor_sync(0xFFFFFFFFu, sk_loc, off);
    }

    // Per-row scalar tail, computed redundantly by all 32 lanes (warp-wide
    // issue: same cost as 1 lane, no broadcast needed).
    const float c = __ldg(curvature);
    const float sqrt_c = sqrtf(c);
    const float inv_keep = 1.0f / (1.0f - RATE);

    float arg = sqrtf(c + s_loc) / sqrt_c - EPS;
    arg = fmaxf(arg, ACOSH_MIN);
    // acosh(x) = log(x + sqrt(x^2 - 1)); arg >= 1.0001 so stable.
    float dist = sqrt_c * __logf(arg + sqrtf(fmaf(arg, arg, -1.0f)));
    float scale1 = dist / (sqrtf(s_loc) + EPS);

    float t = scale1 * scale1 * sk_loc * (inv_keep * inv_keep);
    float snv = sqrtf(t) / sqrt_c + EPS;
    float snv_c = fminf(fmaxf(snv, -CLIP_MAG), CLIP_MAG);

    float e  = __expf(snv_c);
    float ei = 1.0f / e;
    float cosh_v = 0.5f * (e + ei);
    float sinh_v = 0.5f * (e - ei);

    const float oscale    = (sinh_v / snv) * scale1 * inv_keep;
    const float first_val = cosh_v * sqrt_c;

    // Output pass: reconstruct dropped values from the bitmask.
    // Streaming stores (evict-first): output is never read.
    #pragma unroll
    for (int i = 0; i < 2; i++) {
        #pragma unroll
        for (int h = 0; h < 2; h++) {       // two float4s per 8-float chunk
            float4 r;
            int jb = 8*i + 4*h;
            r.x = (bits & (1u << (jb+0))) ? oscale * v[i].f[4*h+0] : 0.0f;
            r.y = (bits & (1u << (jb+1))) ? oscale * v[i].f[4*h+1] : 0.0f;
            r.z = (bits & (1u << (jb+2))) ? oscale * v[i].f[4*h+2] : 0.0f;
            r.w = (bits & (1u << (jb+3))) ? oscale * v[i].f[4*h+3] : 0.0f;
            if (i == 0 && h == 0 && lane == 0) r.x = first_val;  // out[row][0]
            __stcs(reinterpret_cast<float4*>(op + i * 256 + lane * 8 + h * 4), r);
        }
    }
}

extern "C" void kernel_launch(void* const* d_in, const int* in_sizes, int n_in,
                              void* d_out, int out_size)
{
    const float* vecs      = (const float*)d_in[0];
    const float* curvature = (const float*)d_in[1];
    const float* mask_u    = (const float*)d_in[2];
    float* out = (float*)d_out;

    const int n_rows = in_sizes[0] / D;                 // 16384
    const int blocks = n_rows / ROWS_PER_BLOCK;         // 2048
    dropout_hyperbolic_kernel<<<blocks, THREADS>>>(vecs, curvature, mask_u, out);
}